// round 10
// baseline (speedup 1.0000x reference)
#include <cuda_runtime.h>
#include <cuda_fp16.h>
#include <math.h>

// ---------------------------------------------------------------------------
// SHINE heterogeneous GCN — CSR counting sort (hist fused into prep),
// fp16-staged gather SpMM (MLP-4, fp32 accumulate), register-tiled GEMM,
// fused doc-agg + L2 norm.
// ---------------------------------------------------------------------------
#define N_DOC    10000
#define N_WORD   20000
#define N_ENT    10000
#define N_POS    60
#define DIM      128
#define D_POS_IN 60
#define D_WEMB   300
#define EPSN     1e-9f

#define E11 320000
#define E22 160000
#define E33 3600
#define E01 300000
#define E02 100000
#define E03 150000
#define TOT_E (E11 + E22 + E33 + E01 + E02 + E03)   // 1,033,600

// Counter-segment bases (order: a11, a22, a33, a01, a02, a03)
#define C11 0
#define C22 (C11 + N_WORD)   // 20000
#define C33 (C22 + N_ENT)    // 30000
#define C01 (C33 + N_POS)    // 30060
#define C02 (C01 + N_DOC)    // 40060
#define C03 (C02 + N_DOC)    // 50060
#define CTOT (C03 + N_DOC)   // 60060

// Edge-buffer segment bases (all even)
#define B11 0
#define B22 (B11 + E11)
#define B33 (B22 + E22)
#define B01 (B33 + E33)
#define B02 (B01 + E01)
#define B03 (B02 + E02)

// ---------------------------------------------------------------------------
// static scratch
__device__ __align__(16) float2 g_sorted[TOT_E];   // row-sorted (col_bits, val)
__device__ __align__(16) int    g_cnt[CTOT];
__device__ __align__(16) int    g_off[CTOT];       // after bucket: inclusive prefix

// fp16-staged gather sources
__device__ __align__(16) __half g_f1h  [N_WORD * DIM];
__device__ __align__(16) __half g_f2h  [N_ENT  * DIM];
__device__ __align__(16) __half g_wembh[N_ENT  * D_WEMB];
__device__ __align__(16) __half g_g1   [N_WORD * DIM];
__device__ __align__(16) __half g_g2   [N_ENT  * DIM];
__device__ __align__(16) __half g_g3   [N_POS  * DIM];
__device__ __align__(16) __half g_g3b  [N_POS  * DIM];
__device__ __align__(16) __half g_tmpB [N_WORD * DIM];
__device__ __align__(16) __half g_tmp2b[N_ENT  * DIM];
__device__ __align__(16) __half g_tmp3b[N_POS  * DIM];

// fp32 GEMM inputs (read linearly, not gathered)
__device__ __align__(16) float g_tmpA[N_WORD * DIM];
__device__ __align__(16) float g_tmp2[N_ENT  * DIM];
__device__ __align__(16) float g_tmp3[N_POS  * DIM];

struct EdgePtrs {
    const int *r11, *c11; const float *v11;
    const int *r22, *c22; const float *v22;
    const int *r33, *c33; const float *v33;
    const int *r01, *c01; const float *v01;
    const int *r02, *c02; const float *v02;
    const int *r03, *c03; const float *v03;
};

// ---------------------------------------------------------------------------
__device__ __forceinline__ float4 relu4(float4 t) {
    t.x = fmaxf(t.x, 0.f); t.y = fmaxf(t.y, 0.f);
    t.z = fmaxf(t.z, 0.f); t.w = fmaxf(t.w, 0.f);
    return t;
}
__device__ __forceinline__ void fma4(float4& a, float s, float4 t) {
    a.x = fmaf(s, t.x, a.x); a.y = fmaf(s, t.y, a.y);
    a.z = fmaf(s, t.z, a.z); a.w = fmaf(s, t.w, a.w);
}
__device__ __forceinline__ void add4(float4& a, float4 t) {
    a.x += t.x; a.y += t.y; a.z += t.z; a.w += t.w;
}
__device__ __forceinline__ float dot4(float4 a) {
    return a.x * a.x + a.y * a.y + a.z * a.z + a.w * a.w;
}
// 8B load of 4 halves -> float4
__device__ __forceinline__ float4 ldg_h4(const __half* base, int unit) {
    uint2 u = __ldg((const uint2*)base + unit);
    __half2 a = *reinterpret_cast<__half2*>(&u.x);
    __half2 b = *reinterpret_cast<__half2*>(&u.y);
    float2 fa = __half22float2(a), fb = __half22float2(b);
    return make_float4(fa.x, fa.y, fb.x, fb.y);
}
__device__ __forceinline__ void st_h4(__half* base, int unit, float4 v) {
    __half2 a = __floats2half2_rn(v.x, v.y);
    __half2 b = __floats2half2_rn(v.z, v.w);
    uint2 u;
    u.x = *reinterpret_cast<unsigned*>(&a);
    u.y = *reinterpret_cast<unsigned*>(&b);
    ((uint2*)base)[unit] = u;
}

// ---------------------------------------------------------------------------
// gather SpMM row accumulator over fp16 source; warp-per-row, float4/lane.
// 4 edges in flight (independent index loads + gathers + accumulators).
template <bool RELU>
__device__ __forceinline__ float4 spmm_row_acc_h(int gi, const __half* __restrict__ x, int lane) {
    int s = (gi == 0) ? 0 : __ldg(g_off + gi - 1);
    int e = __ldg(g_off + gi);
    float4 a0 = make_float4(0.f, 0.f, 0.f, 0.f);
    float4 a1 = a0, a2 = a0, a3 = a0;
    int k = s;
    for (; k + 3 < e; k += 4) {
        float2 c0 = __ldg(&g_sorted[k + 0]);
        float2 c1 = __ldg(&g_sorted[k + 1]);
        float2 c2 = __ldg(&g_sorted[k + 2]);
        float2 c3 = __ldg(&g_sorted[k + 3]);
        float4 t0 = ldg_h4(x + (size_t)__float_as_int(c0.x) * DIM, lane);
        float4 t1 = ldg_h4(x + (size_t)__float_as_int(c1.x) * DIM, lane);
        float4 t2 = ldg_h4(x + (size_t)__float_as_int(c2.x) * DIM, lane);
        float4 t3 = ldg_h4(x + (size_t)__float_as_int(c3.x) * DIM, lane);
        if (RELU) { t0 = relu4(t0); t1 = relu4(t1); t2 = relu4(t2); t3 = relu4(t3); }
        fma4(a0, c0.y, t0); fma4(a1, c1.y, t1);
        fma4(a2, c2.y, t2); fma4(a3, c3.y, t3);
    }
    for (; k < e; ++k) {
        float2 cv = __ldg(&g_sorted[k]);
        float4 t = ldg_h4(x + (size_t)__float_as_int(cv.x) * DIM, lane);
        if (RELU) t = relu4(t);
        fma4(a0, cv.y, t);
    }
    add4(a0, a1); add4(a2, a3); add4(a0, a2);
    return a0;
}

// ---------------------------------------------------------------------------
// register-tiled GEMM: one warp computes 4 rows x 128 cols, output fp32 or fp16
__device__ __forceinline__ void gemm_store(float* p, int lane, float4 v) {
    ((float4*)p)[lane] = v;
}
__device__ __forceinline__ void gemm_store(__half* p, int lane, float4 v) {
    st_h4(p, lane, v);
}

template <bool RELU_A, typename OutT>
__device__ __forceinline__ void gemm4_rows(const float* __restrict__ A,
                                           const float* __restrict__ W,
                                           const float* __restrict__ bias,
                                           OutT* __restrict__ C,
                                           int r0, int K, int lane)
{
    float4 a0 = make_float4(0,0,0,0), a1 = a0, a2 = a0, a3 = a0;
    if (4 * lane < K) {
        a0 = *(const float4*)(A + (size_t)(r0 + 0) * K + 4 * lane);
        a1 = *(const float4*)(A + (size_t)(r0 + 1) * K + 4 * lane);
        a2 = *(const float4*)(A + (size_t)(r0 + 2) * K + 4 * lane);
        a3 = *(const float4*)(A + (size_t)(r0 + 3) * K + 4 * lane);
        if (RELU_A) { a0 = relu4(a0); a1 = relu4(a1); a2 = relu4(a2); a3 = relu4(a3); }
    }
    float4 bf = __ldg((const float4*)bias + lane);
    float4 c0 = bf, c1 = bf, c2 = bf, c3 = bf;

    for (int k = 0; k < K; k += 4) {
        int src = k >> 2;
        #pragma unroll
        for (int kk = 0; kk < 4; kk++) {
            float4 wv = __ldg((const float4*)(W + (size_t)(k + kk) * DIM) + lane);
            float s0 = __shfl_sync(0xffffffffu, ((const float*)&a0)[kk], src);
            float s1 = __shfl_sync(0xffffffffu, ((const float*)&a1)[kk], src);
            float s2 = __shfl_sync(0xffffffffu, ((const float*)&a2)[kk], src);
            float s3 = __shfl_sync(0xffffffffu, ((const float*)&a3)[kk], src);
            fma4(c0, s0, wv); fma4(c1, s1, wv); fma4(c2, s2, wv); fma4(c3, s3, wv);
        }
    }
    gemm_store(C + (size_t)(r0 + 0) * DIM, lane, c0);
    gemm_store(C + (size_t)(r0 + 1) * DIM, lane, c1);
    gemm_store(C + (size_t)(r0 + 2) * DIM, lane, c2);
    gemm_store(C + (size_t)(r0 + 3) * DIM, lane, c3);
}

// ---------------------------------------------------------------------------
// 0) prep: histogram (blocks [0,GB_HIST)) + fp16 conversion of f1/f2/word_emb
//    (blocks [GB_HIST, GB_HIST+GB_CONV)) + POS layer-1 GEMM (last block).
//    g_cnt is zeroed by a cudaMemsetAsync before this kernel.
#define F1U  (N_WORD * DIM / 4)      // 640000
#define F2U  (N_ENT  * DIM / 4)      // 320000
#define WEU  (N_ENT  * D_WEMB / 4)   // 750000
#define CONV_UNITS (F1U + F2U + WEU) // 1,710,000
#define GB_HIST ((TOT_E + 255) / 256)     // 4038
#define GB_CONV 2048

__global__ void prep_kernel(EdgePtrs ep,
                            const float* __restrict__ f1, const float* __restrict__ f2,
                            const float* __restrict__ wemb, const float* __restrict__ f3,
                            const float* __restrict__ W3, const float* __restrict__ b3)
{
    int b = blockIdx.x;
    if (b < GB_HIST) {
        // histogram
        int e = b * blockDim.x + threadIdx.x;
        if (e >= TOT_E) return;
        int gi;
        if      (e < B22) gi = C11 + __ldg(ep.r11 + (e - B11));
        else if (e < B33) gi = C22 + __ldg(ep.r22 + (e - B22));
        else if (e < B01) gi = C33 + __ldg(ep.r33 + (e - B33));
        else if (e < B02) gi = C01 + __ldg(ep.r01 + (e - B01));
        else if (e < B03) gi = C02 + __ldg(ep.r02 + (e - B02));
        else              gi = C03 + __ldg(ep.r03 + (e - B03));
        atomicAdd(g_cnt + gi, 1);
    } else if (b < GB_HIST + GB_CONV) {
        int stride = GB_CONV * blockDim.x;
        for (int u = (b - GB_HIST) * blockDim.x + threadIdx.x; u < CONV_UNITS; u += stride) {
            if (u < F1U) {
                st_h4(g_f1h, u, __ldg((const float4*)f1 + u));
            } else if (u < F1U + F2U) {
                int i = u - F1U;
                st_h4(g_f2h, i, __ldg((const float4*)f2 + i));
            } else {
                int i = u - (F1U + F2U);
                st_h4(g_wembh, i, __ldg((const float4*)wemb + i));
            }
        }
    } else {
        // POS layer-1 GEMM: 60 rows -> 15 warp-tasks, 8 warps in this block
        int lane = threadIdx.x & 31;
        for (int w = threadIdx.x >> 5; w < N_POS / 4; w += blockDim.x >> 5)
            gemm4_rows<false>(f3, W3, b3, g_g3, 4 * w, D_POS_IN, lane);
    }
}

// ---------------------------------------------------------------------------
// 1) single-block exclusive scan of the counters -> g_off
__global__ void scan_kernel() {
    __shared__ int sp[1024];
    const int tid = threadIdx.x;
    const int per = (CTOT + 1023) / 1024;   // 59
    int lo = tid * per;
    int hi = lo + per; if (hi > CTOT) hi = CTOT;
    if (lo > CTOT) lo = CTOT;
    int s = 0;
    for (int i = lo; i < hi; i++) s += g_cnt[i];
    sp[tid] = s;
    __syncthreads();
    for (int d = 1; d < 1024; d <<= 1) {
        int v = (tid >= d) ? sp[tid - d] : 0;
        __syncthreads();
        sp[tid] += v;
        __syncthreads();
    }
    int run = (tid > 0) ? sp[tid - 1] : 0;
    for (int i = lo; i < hi; i++) {
        g_off[i] = run;
        run += g_cnt[i];
    }
}

// 2) bucket scatter, 2 edges per thread (vectorized loads, 2 independent
//    atomic->store chains); bumps g_off in place (-> inclusive prefix).
__global__ void bucket_kernel(EdgePtrs ep) {
    int p = blockIdx.x * blockDim.x + threadIdx.x;   // pair index
    if (p >= TOT_E / 2) return;
    int e = 2 * p;
    const int *rp, *cp; const float *vp; int cb;
    if (e < B22)      { rp = ep.r11; cp = ep.c11; vp = ep.v11; cb = C11; e -= B11; }
    else if (e < B33) { rp = ep.r22; cp = ep.c22; vp = ep.v22; cb = C22; e -= B22; }
    else if (e < B01) { rp = ep.r33; cp = ep.c33; vp = ep.v33; cb = C33; e -= B33; }
    else if (e < B02) { rp = ep.r01; cp = ep.c01; vp = ep.v01; cb = C01; e -= B01; }
    else if (e < B03) { rp = ep.r02; cp = ep.c02; vp = ep.v02; cb = C02; e -= B02; }
    else              { rp = ep.r03; cp = ep.c03; vp = ep.v03; cb = C03; e -= B03; }
    int h = e >> 1;
    int2   r = __ldg((const int2*)rp + h);
    int2   c = __ldg((const int2*)cp + h);
    float2 v = __ldg((const float2*)vp + h);
    int pos0 = atomicAdd(g_off + cb + r.x, 1);
    int pos1 = atomicAdd(g_off + cb + r.y, 1);
    g_sorted[pos0] = make_float2(__int_as_float(c.x), v.x);
    g_sorted[pos1] = make_float2(__int_as_float(c.y), v.y);
}

// ---------------------------------------------------------------------------
// 3/5) fused layer-1 / layer-2 SpMM over all three node types
template <int LAYER>
__global__ void spmm_l_kernel() {
    int w    = (blockIdx.x * blockDim.x + threadIdx.x) >> 5;
    int lane = threadIdx.x & 31;
    if (w >= N_WORD + N_ENT + N_POS) return;
    const __half* x; void* outp; int gi;
    if (w < N_WORD) {
        gi = C11 + w;
        x = (LAYER == 1) ? g_f1h : g_g1;
        outp = (LAYER == 1) ? (void*)(g_tmpA + (size_t)w * DIM)
                            : (void*)(g_tmpB + (size_t)w * DIM);
    } else if (w < N_WORD + N_ENT) {
        int r = w - N_WORD;
        gi = C22 + r;
        x = (LAYER == 1) ? g_f2h : g_g2;
        outp = (LAYER == 1) ? (void*)(g_tmp2 + (size_t)r * DIM)
                            : (void*)(g_tmp2b + (size_t)r * DIM);
    } else {
        int r = w - (N_WORD + N_ENT);
        gi = C33 + r;
        x = (LAYER == 1) ? g_g3 : g_g3b;
        outp = (LAYER == 1) ? (void*)(g_tmp3 + (size_t)r * DIM)
                            : (void*)(g_tmp3b + (size_t)r * DIM);
    }
    float4 acc = spmm_row_acc_h<false>(gi, x, lane);
    if (LAYER == 1) ((float4*)outp)[lane] = acc;
    else            st_h4((__half*)outp, lane, acc);
}

// 4) fused layer-2 projections for all three types (relu on input): K=128
__global__ void gemm_l2_kernel(const float* __restrict__ W1, const float* __restrict__ b1,
                               const float* __restrict__ W2, const float* __restrict__ b2,
                               const float* __restrict__ Wp, const float* __restrict__ bp) {
    int w    = (blockIdx.x * blockDim.x + threadIdx.x) >> 5;
    int lane = threadIdx.x & 31;
    const int WW = N_WORD / 4, WE = WW + N_ENT / 4, WP = WE + N_POS / 4;
    if (w >= WP) return;
    if (w < WW)       gemm4_rows<true>(g_tmpA, W1, b1, g_g1,  4 * w,        DIM, lane);
    else if (w < WE)  gemm4_rows<true>(g_tmp2, W2, b2, g_g2,  4 * (w - WW), DIM, lane);
    else              gemm4_rows<true>(g_tmp3, Wp, bp, g_g3b, 4 * (w - WE), DIM, lane);
}

// ---------------------------------------------------------------------------
// 6) fused doc aggregation + relu(source) + wemb concat + L2 norm
__global__ void docagg_kernel(float* __restrict__ out) {
    int w    = (blockIdx.x * blockDim.x + threadIdx.x) >> 5;
    int lane = threadIdx.x & 31;
    if (w >= 3 * N_DOC) return;
    float* out1 = out;
    float* out2 = out + (size_t)N_DOC * DIM;
    float* out3 = out2 + (size_t)N_DOC * (DIM + D_WEMB);

    if (w < N_DOC || w >= 2 * N_DOC) {
        bool first = (w < N_DOC);
        int row = first ? w : (w - 2 * N_DOC);
        int gi  = first ? (C01 + row) : (C03 + row);
        const __half* x = first ? g_tmpB : g_tmp3b;
        float4 acc = spmm_row_acc_h<true>(gi, x, lane);
        float ss = dot4(acc);
        #pragma unroll
        for (int o = 16; o; o >>= 1) ss += __shfl_xor_sync(0xffffffffu, ss, o);
        float inv = 1.f / (sqrtf(ss) + EPSN);
        float* dst = (first ? out1 : out3) + (size_t)row * DIM;
        ((float4*)dst)[lane] = make_float4(acc.x*inv, acc.y*inv, acc.z*inv, acc.w*inv);
    } else {
        // entities -> out2: 128 feature cols + 300 word_emb cols, norm over 428
        int row = w - N_DOC;
        int gi = C02 + row;
        int s = __ldg(g_off + gi - 1);
        int e = __ldg(g_off + gi);
        float4 aF = make_float4(0,0,0,0), w0 = aF, w1 = aF, w2 = aF;
        #pragma unroll 2
        for (int k = s; k < e; ++k) {
            float2 cv = __ldg(&g_sorted[k]);
            int c = __float_as_int(cv.x);
            float v = cv.y;
            float4 t = relu4(ldg_h4(g_tmp2b + (size_t)c * DIM, lane));
            fma4(aF, v, t);
            const __half* ws = g_wembh + (size_t)c * D_WEMB;  // 75 h4-units
            fma4(w0, v, ldg_h4(ws, lane));
            fma4(w1, v, ldg_h4(ws, lane + 32));
            if (lane < 11) fma4(w2, v, ldg_h4(ws, lane + 64));
        }
        float ss = dot4(aF) + dot4(w0) + dot4(w1);
        if (lane < 11) ss += dot4(w2);
        #pragma unroll
        for (int o = 16; o; o >>= 1) ss += __shfl_xor_sync(0xffffffffu, ss, o);
        float inv = 1.f / (sqrtf(ss) + EPSN);
        float* rowp = out2 + (size_t)row * (DIM + D_WEMB);
        ((float4*)rowp)[lane] = make_float4(aF.x*inv, aF.y*inv, aF.z*inv, aF.w*inv);
        float4* wr = (float4*)(rowp + DIM);
        wr[lane]      = make_float4(w0.x*inv, w0.y*inv, w0.z*inv, w0.w*inv);
        wr[lane + 32] = make_float4(w1.x*inv, w1.y*inv, w1.z*inv, w1.w*inv);
        if (lane < 11)
            wr[lane + 64] = make_float4(w2.x*inv, w2.y*inv, w2.z*inv, w2.w*inv);
    }
}

// ---------------------------------------------------------------------------
extern "C" void kernel_launch(void* const* d_in, const int* in_sizes, int n_in,
                              void* d_out, int out_size)
{
    const float* f1       = (const float*)d_in[0];
    const float* f2       = (const float*)d_in[1];
    const float* f3       = (const float*)d_in[2];
    const float* word_emb = (const float*)d_in[3];

    EdgePtrs ep;
    ep.r11 = (const int*)d_in[4];  ep.c11 = (const int*)d_in[5];  ep.v11 = (const float*)d_in[6];
    ep.r22 = (const int*)d_in[7];  ep.c22 = (const int*)d_in[8];  ep.v22 = (const float*)d_in[9];
    ep.r33 = (const int*)d_in[10]; ep.c33 = (const int*)d_in[11]; ep.v33 = (const float*)d_in[12];
    ep.r01 = (const int*)d_in[13]; ep.c01 = (const int*)d_in[14]; ep.v01 = (const float*)d_in[15];
    ep.r02 = (const int*)d_in[16]; ep.c02 = (const int*)d_in[17]; ep.v02 = (const float*)d_in[18];
    ep.r03 = (const int*)d_in[19]; ep.c03 = (const int*)d_in[20]; ep.v03 = (const float*)d_in[21];

    const float* W3   = (const float*)d_in[22];
    const float* b3   = (const float*)d_in[23];
    const float* W1_2 = (const float*)d_in[24];
    const float* b1_2 = (const float*)d_in[25];
    const float* W2_2 = (const float*)d_in[26];
    const float* b2_2 = (const float*)d_in[27];
    const float* W3_2 = (const float*)d_in[28];
    const float* b3_2 = (const float*)d_in[29];

    void* cnt_addr = nullptr;
    cudaGetSymbolAddress(&cnt_addr, g_cnt);

    const int TB = 256;
    const int GRID_PREP = GB_HIST + GB_CONV + 1;
    const int GRID_BKT  = (TOT_E / 2 + TB - 1) / TB;
    const int GRID_SPMM = ((N_WORD + N_ENT + N_POS) * 32 + TB - 1) / TB;
    const int GRID_GEMM = (((N_WORD + N_ENT + N_POS) / 4) * 32 + TB - 1) / TB;
    const int GRID_DOC  = (3 * N_DOC * 32 + TB - 1) / TB;

    cudaMemsetAsync(cnt_addr, 0, CTOT * sizeof(int), 0);
    prep_kernel<<<GRID_PREP, TB>>>(ep, f1, f2, word_emb, f3, W3, b3);
    scan_kernel<<<1, 1024>>>();
    bucket_kernel<<<GRID_BKT, TB>>>(ep);

    spmm_l_kernel<1><<<GRID_SPMM, TB>>>();
    gemm_l2_kernel<<<GRID_GEMM, TB>>>(W1_2, b1_2, W2_2, b2_2, W3_2, b3_2);
    spmm_l_kernel<2><<<GRID_SPMM, TB>>>();

    docagg_kernel<<<GRID_DOC, TB>>>((float*)d_out);
}

// round 11
// speedup vs baseline: 1.4087x; 1.4087x over previous
#include <cuda_runtime.h>
#include <cuda_fp16.h>
#include <math.h>

// ---------------------------------------------------------------------------
// SHINE heterogeneous GCN — CSR counting sort, fp16-staged gather SpMM
// (fp32 accumulate, 2-acc + index prefetch), register-tiled GEMM,
// fused doc-agg + L2 norm.  (Revert of the MLP-4 / fused-hist experiment.)
// ---------------------------------------------------------------------------
#define N_DOC    10000
#define N_WORD   20000
#define N_ENT    10000
#define N_POS    60
#define DIM      128
#define D_POS_IN 60
#define D_WEMB   300
#define EPSN     1e-9f

#define E11 320000
#define E22 160000
#define E33 3600
#define E01 300000
#define E02 100000
#define E03 150000
#define TOT_E (E11 + E22 + E33 + E01 + E02 + E03)   // 1,033,600

// Counter-segment bases (order: a11, a22, a33, a01, a02, a03)
#define C11 0
#define C22 (C11 + N_WORD)   // 20000
#define C33 (C22 + N_ENT)    // 30000
#define C01 (C33 + N_POS)    // 30060
#define C02 (C01 + N_DOC)    // 40060
#define C03 (C02 + N_DOC)    // 50060
#define CTOT (C03 + N_DOC)   // 60060

// Edge-buffer segment bases (all even)
#define B11 0
#define B22 (B11 + E11)
#define B33 (B22 + E22)
#define B01 (B33 + E33)
#define B02 (B01 + E01)
#define B03 (B02 + E02)

// ---------------------------------------------------------------------------
// static scratch
__device__ __align__(16) float2 g_sorted[TOT_E];   // row-sorted (col_bits, val)
__device__ __align__(16) int    g_cnt[CTOT];
__device__ __align__(16) int    g_off[CTOT];       // after bucket: inclusive prefix

// fp16-staged gather sources
__device__ __align__(16) __half g_f1h  [N_WORD * DIM];
__device__ __align__(16) __half g_f2h  [N_ENT  * DIM];
__device__ __align__(16) __half g_wembh[N_ENT  * D_WEMB];
__device__ __align__(16) __half g_g1   [N_WORD * DIM];
__device__ __align__(16) __half g_g2   [N_ENT  * DIM];
__device__ __align__(16) __half g_g3   [N_POS  * DIM];
__device__ __align__(16) __half g_g3b  [N_POS  * DIM];
__device__ __align__(16) __half g_tmpB [N_WORD * DIM];
__device__ __align__(16) __half g_tmp2b[N_ENT  * DIM];
__device__ __align__(16) __half g_tmp3b[N_POS  * DIM];

// fp32 GEMM inputs (read linearly, not gathered)
__device__ __align__(16) float g_tmpA[N_WORD * DIM];
__device__ __align__(16) float g_tmp2[N_ENT  * DIM];
__device__ __align__(16) float g_tmp3[N_POS  * DIM];

struct EdgePtrs {
    const int *r11, *c11; const float *v11;
    const int *r22, *c22; const float *v22;
    const int *r33, *c33; const float *v33;
    const int *r01, *c01; const float *v01;
    const int *r02, *c02; const float *v02;
    const int *r03, *c03; const float *v03;
};

// ---------------------------------------------------------------------------
__device__ __forceinline__ float4 relu4(float4 t) {
    t.x = fmaxf(t.x, 0.f); t.y = fmaxf(t.y, 0.f);
    t.z = fmaxf(t.z, 0.f); t.w = fmaxf(t.w, 0.f);
    return t;
}
__device__ __forceinline__ void fma4(float4& a, float s, float4 t) {
    a.x = fmaf(s, t.x, a.x); a.y = fmaf(s, t.y, a.y);
    a.z = fmaf(s, t.z, a.z); a.w = fmaf(s, t.w, a.w);
}
__device__ __forceinline__ float dot4(float4 a) {
    return a.x * a.x + a.y * a.y + a.z * a.z + a.w * a.w;
}
// 8B load of 4 halves -> float4
__device__ __forceinline__ float4 ldg_h4(const __half* base, int unit) {
    uint2 u = __ldg((const uint2*)base + unit);
    __half2 a = *reinterpret_cast<__half2*>(&u.x);
    __half2 b = *reinterpret_cast<__half2*>(&u.y);
    float2 fa = __half22float2(a), fb = __half22float2(b);
    return make_float4(fa.x, fa.y, fb.x, fb.y);
}
__device__ __forceinline__ void st_h4(__half* base, int unit, float4 v) {
    __half2 a = __floats2half2_rn(v.x, v.y);
    __half2 b = __floats2half2_rn(v.z, v.w);
    uint2 u;
    u.x = *reinterpret_cast<unsigned*>(&a);
    u.y = *reinterpret_cast<unsigned*>(&b);
    ((uint2*)base)[unit] = u;
}

// ---------------------------------------------------------------------------
// register-tiled GEMM: one warp computes 4 rows x 128 cols, output fp32 or fp16
__device__ __forceinline__ void gemm_store(float* p, int lane, float4 v) {
    ((float4*)p)[lane] = v;
}
__device__ __forceinline__ void gemm_store(__half* p, int lane, float4 v) {
    st_h4(p, lane, v);
}

template <bool RELU_A, typename OutT>
__device__ __forceinline__ void gemm4_rows(const float* __restrict__ A,
                                           const float* __restrict__ W,
                                           const float* __restrict__ bias,
                                           OutT* __restrict__ C,
                                           int r0, int K, int lane)
{
    float4 a0 = make_float4(0,0,0,0), a1 = a0, a2 = a0, a3 = a0;
    if (4 * lane < K) {
        a0 = *(const float4*)(A + (size_t)(r0 + 0) * K + 4 * lane);
        a1 = *(const float4*)(A + (size_t)(r0 + 1) * K + 4 * lane);
        a2 = *(const float4*)(A + (size_t)(r0 + 2) * K + 4 * lane);
        a3 = *(const float4*)(A + (size_t)(r0 + 3) * K + 4 * lane);
        if (RELU_A) { a0 = relu4(a0); a1 = relu4(a1); a2 = relu4(a2); a3 = relu4(a3); }
    }
    float4 bf = __ldg((const float4*)bias + lane);
    float4 c0 = bf, c1 = bf, c2 = bf, c3 = bf;

    for (int k = 0; k < K; k += 4) {
        int src = k >> 2;
        #pragma unroll
        for (int kk = 0; kk < 4; kk++) {
            float4 wv = __ldg((const float4*)(W + (size_t)(k + kk) * DIM) + lane);
            float s0 = __shfl_sync(0xffffffffu, ((const float*)&a0)[kk], src);
            float s1 = __shfl_sync(0xffffffffu, ((const float*)&a1)[kk], src);
            float s2 = __shfl_sync(0xffffffffu, ((const float*)&a2)[kk], src);
            float s3 = __shfl_sync(0xffffffffu, ((const float*)&a3)[kk], src);
            fma4(c0, s0, wv); fma4(c1, s1, wv); fma4(c2, s2, wv); fma4(c3, s3, wv);
        }
    }
    gemm_store(C + (size_t)(r0 + 0) * DIM, lane, c0);
    gemm_store(C + (size_t)(r0 + 1) * DIM, lane, c1);
    gemm_store(C + (size_t)(r0 + 2) * DIM, lane, c2);
    gemm_store(C + (size_t)(r0 + 3) * DIM, lane, c3);
}

// ---------------------------------------------------------------------------
// 0) prep: zero counters + convert f1/f2/word_emb to fp16 + POS layer-1 GEMM
#define CNT4 (CTOT / 4)              // 15015
#define F1U  (N_WORD * DIM / 4)      // 640000
#define F2U  (N_ENT  * DIM / 4)      // 320000
#define WEU  (N_ENT  * D_WEMB / 4)   // 750000
#define PREP_UNITS (CNT4 + F1U + F2U + WEU)

__global__ void prep_kernel(const float* __restrict__ f1, const float* __restrict__ f2,
                            const float* __restrict__ wemb, const float* __restrict__ f3,
                            const float* __restrict__ W3, const float* __restrict__ b3)
{
    if (blockIdx.x == 0) {
        int lane = threadIdx.x & 31;
        for (int w = threadIdx.x >> 5; w < N_POS / 4; w += blockDim.x >> 5)
            gemm4_rows<false>(f3, W3, b3, g_g3, 4 * w, D_POS_IN, lane);
        return;
    }
    int stride = (gridDim.x - 1) * blockDim.x;
    for (int u = (blockIdx.x - 1) * blockDim.x + threadIdx.x; u < PREP_UNITS; u += stride) {
        if (u < CNT4) {
            ((int4*)g_cnt)[u] = make_int4(0, 0, 0, 0);
        } else if (u < CNT4 + F1U) {
            int i = u - CNT4;
            st_h4(g_f1h, i, __ldg((const float4*)f1 + i));
        } else if (u < CNT4 + F1U + F2U) {
            int i = u - (CNT4 + F1U);
            st_h4(g_f2h, i, __ldg((const float4*)f2 + i));
        } else {
            int i = u - (CNT4 + F1U + F2U);
            st_h4(g_wembh, i, __ldg((const float4*)wemb + i));
        }
    }
}

// ---------------------------------------------------------------------------
// 1) fused histogram over all 6 adjacencies
__global__ void hist_kernel(EdgePtrs ep) {
    int e = blockIdx.x * blockDim.x + threadIdx.x;
    if (e >= TOT_E) return;
    int gi;
    if      (e < B22) gi = C11 + __ldg(ep.r11 + (e - B11));
    else if (e < B33) gi = C22 + __ldg(ep.r22 + (e - B22));
    else if (e < B01) gi = C33 + __ldg(ep.r33 + (e - B33));
    else if (e < B02) gi = C01 + __ldg(ep.r01 + (e - B01));
    else if (e < B03) gi = C02 + __ldg(ep.r02 + (e - B02));
    else              gi = C03 + __ldg(ep.r03 + (e - B03));
    atomicAdd(g_cnt + gi, 1);
}

// 2) single-block exclusive scan of the counters -> g_off
__global__ void scan_kernel() {
    __shared__ int sp[1024];
    const int tid = threadIdx.x;
    const int per = (CTOT + 1023) / 1024;   // 59
    int lo = tid * per;
    int hi = lo + per; if (hi > CTOT) hi = CTOT;
    if (lo > CTOT) lo = CTOT;
    int s = 0;
    for (int i = lo; i < hi; i++) s += g_cnt[i];
    sp[tid] = s;
    __syncthreads();
    for (int d = 1; d < 1024; d <<= 1) {
        int v = (tid >= d) ? sp[tid - d] : 0;
        __syncthreads();
        sp[tid] += v;
        __syncthreads();
    }
    int run = (tid > 0) ? sp[tid - 1] : 0;
    for (int i = lo; i < hi; i++) {
        g_off[i] = run;
        run += g_cnt[i];
    }
}

// 3) bucket scatter, 2 edges per thread (vectorized loads, 2 independent
//    atomic->store chains); bumps g_off in place (-> inclusive prefix).
__global__ void bucket_kernel(EdgePtrs ep) {
    int p = blockIdx.x * blockDim.x + threadIdx.x;   // pair index
    if (p >= TOT_E / 2) return;
    int e = 2 * p;
    const int *rp, *cp; const float *vp; int cb;
    if (e < B22)      { rp = ep.r11; cp = ep.c11; vp = ep.v11; cb = C11; e -= B11; }
    else if (e < B33) { rp = ep.r22; cp = ep.c22; vp = ep.v22; cb = C22; e -= B22; }
    else if (e < B01) { rp = ep.r33; cp = ep.c33; vp = ep.v33; cb = C33; e -= B33; }
    else if (e < B02) { rp = ep.r01; cp = ep.c01; vp = ep.v01; cb = C01; e -= B01; }
    else if (e < B03) { rp = ep.r02; cp = ep.c02; vp = ep.v02; cb = C02; e -= B02; }
    else              { rp = ep.r03; cp = ep.c03; vp = ep.v03; cb = C03; e -= B03; }
    int h = e >> 1;
    int2   r = __ldg((const int2*)rp + h);
    int2   c = __ldg((const int2*)cp + h);
    float2 v = __ldg((const float2*)vp + h);
    int pos0 = atomicAdd(g_off + cb + r.x, 1);
    int pos1 = atomicAdd(g_off + cb + r.y, 1);
    g_sorted[pos0] = make_float2(__int_as_float(c.x), v.x);
    g_sorted[pos1] = make_float2(__int_as_float(c.y), v.y);
}

// ---------------------------------------------------------------------------
// gather SpMM row accumulator over fp16 source; warp-per-row, float4/lane.
// 2 accumulators + next-pair index prefetch (software pipeline) — the index
// load latency hides under the current iteration's row gathers.
template <bool RELU>
__device__ __forceinline__ float4 spmm_row_acc_h(int gi, const __half* __restrict__ x, int lane) {
    int s = (gi == 0) ? 0 : __ldg(g_off + gi - 1);
    int e = __ldg(g_off + gi);
    float4 acc0 = make_float4(0.f, 0.f, 0.f, 0.f);
    float4 acc1 = acc0;
    int k = s;
    if (k + 1 < e) {
        float2 cv0 = __ldg(&g_sorted[k]);
        float2 cv1 = __ldg(&g_sorted[k + 1]);
        for (; k + 3 < e; k += 2) {
            float2 nv0 = __ldg(&g_sorted[k + 2]);   // prefetch next pair
            float2 nv1 = __ldg(&g_sorted[k + 3]);
            float4 t0 = ldg_h4(x + (size_t)__float_as_int(cv0.x) * DIM, lane);
            float4 t1 = ldg_h4(x + (size_t)__float_as_int(cv1.x) * DIM, lane);
            if (RELU) { t0 = relu4(t0); t1 = relu4(t1); }
            fma4(acc0, cv0.y, t0);
            fma4(acc1, cv1.y, t1);
            cv0 = nv0; cv1 = nv1;
        }
        // drain the held pair
        float4 t0 = ldg_h4(x + (size_t)__float_as_int(cv0.x) * DIM, lane);
        float4 t1 = ldg_h4(x + (size_t)__float_as_int(cv1.x) * DIM, lane);
        if (RELU) { t0 = relu4(t0); t1 = relu4(t1); }
        fma4(acc0, cv0.y, t0);
        fma4(acc1, cv1.y, t1);
        k += 2;
    }
    if (k < e) {
        float2 cv = __ldg(&g_sorted[k]);
        float4 t = ldg_h4(x + (size_t)__float_as_int(cv.x) * DIM, lane);
        if (RELU) t = relu4(t);
        fma4(acc0, cv.y, t);
    }
    acc0.x += acc1.x; acc0.y += acc1.y; acc0.z += acc1.z; acc0.w += acc1.w;
    return acc0;
}

// 4/6) fused layer-1 / layer-2 SpMM over all three node types
template <int LAYER>
__global__ void spmm_l_kernel() {
    int w    = (blockIdx.x * blockDim.x + threadIdx.x) >> 5;
    int lane = threadIdx.x & 31;
    if (w >= N_WORD + N_ENT + N_POS) return;
    const __half* x; void* outp; int gi;
    if (w < N_WORD) {
        gi = C11 + w;
        x = (LAYER == 1) ? g_f1h : g_g1;
        outp = (LAYER == 1) ? (void*)(g_tmpA + (size_t)w * DIM)
                            : (void*)(g_tmpB + (size_t)w * DIM);
    } else if (w < N_WORD + N_ENT) {
        int r = w - N_WORD;
        gi = C22 + r;
        x = (LAYER == 1) ? g_f2h : g_g2;
        outp = (LAYER == 1) ? (void*)(g_tmp2 + (size_t)r * DIM)
                            : (void*)(g_tmp2b + (size_t)r * DIM);
    } else {
        int r = w - (N_WORD + N_ENT);
        gi = C33 + r;
        x = (LAYER == 1) ? g_g3 : g_g3b;
        outp = (LAYER == 1) ? (void*)(g_tmp3 + (size_t)r * DIM)
                            : (void*)(g_tmp3b + (size_t)r * DIM);
    }
    float4 acc = spmm_row_acc_h<false>(gi, x, lane);
    if (LAYER == 1) ((float4*)outp)[lane] = acc;
    else            st_h4((__half*)outp, lane, acc);
}

// 5) fused layer-2 projections for all three types (relu on input): K=128
__global__ void gemm_l2_kernel(const float* __restrict__ W1, const float* __restrict__ b1,
                               const float* __restrict__ W2, const float* __restrict__ b2,
                               const float* __restrict__ Wp, const float* __restrict__ bp) {
    int w    = (blockIdx.x * blockDim.x + threadIdx.x) >> 5;
    int lane = threadIdx.x & 31;
    const int WW = N_WORD / 4, WE = WW + N_ENT / 4, WP = WE + N_POS / 4;
    if (w >= WP) return;
    if (w < WW)       gemm4_rows<true>(g_tmpA, W1, b1, g_g1,  4 * w,        DIM, lane);
    else if (w < WE)  gemm4_rows<true>(g_tmp2, W2, b2, g_g2,  4 * (w - WW), DIM, lane);
    else              gemm4_rows<true>(g_tmp3, Wp, bp, g_g3b, 4 * (w - WE), DIM, lane);
}

// ---------------------------------------------------------------------------
// 7) fused doc aggregation + relu(source) + wemb concat + L2 norm
__global__ void docagg_kernel(float* __restrict__ out) {
    int w    = (blockIdx.x * blockDim.x + threadIdx.x) >> 5;
    int lane = threadIdx.x & 31;
    if (w >= 3 * N_DOC) return;
    float* out1 = out;
    float* out2 = out + (size_t)N_DOC * DIM;
    float* out3 = out2 + (size_t)N_DOC * (DIM + D_WEMB);

    if (w < N_DOC || w >= 2 * N_DOC) {
        bool first = (w < N_DOC);
        int row = first ? w : (w - 2 * N_DOC);
        int gi  = first ? (C01 + row) : (C03 + row);
        const __half* x = first ? g_tmpB : g_tmp3b;
        float4 acc = spmm_row_acc_h<true>(gi, x, lane);
        float ss = dot4(acc);
        #pragma unroll
        for (int o = 16; o; o >>= 1) ss += __shfl_xor_sync(0xffffffffu, ss, o);
        float inv = 1.f / (sqrtf(ss) + EPSN);
        float* dst = (first ? out1 : out3) + (size_t)row * DIM;
        ((float4*)dst)[lane] = make_float4(acc.x*inv, acc.y*inv, acc.z*inv, acc.w*inv);
    } else {
        // entities -> out2: 128 feature cols + 300 word_emb cols, norm over 428
        int row = w - N_DOC;
        int gi = C02 + row;
        int s = __ldg(g_off + gi - 1);
        int e = __ldg(g_off + gi);
        float4 aF = make_float4(0,0,0,0), w0 = aF, w1 = aF, w2 = aF;
        #pragma unroll 2
        for (int k = s; k < e; ++k) {
            float2 cv = __ldg(&g_sorted[k]);
            int c = __float_as_int(cv.x);
            float v = cv.y;
            float4 t = relu4(ldg_h4(g_tmp2b + (size_t)c * DIM, lane));
            fma4(aF, v, t);
            const __half* ws = g_wembh + (size_t)c * D_WEMB;  // 75 h4-units
            fma4(w0, v, ldg_h4(ws, lane));
            fma4(w1, v, ldg_h4(ws, lane + 32));
            if (lane < 11) fma4(w2, v, ldg_h4(ws, lane + 64));
        }
        float ss = dot4(aF) + dot4(w0) + dot4(w1);
        if (lane < 11) ss += dot4(w2);
        #pragma unroll
        for (int o = 16; o; o >>= 1) ss += __shfl_xor_sync(0xffffffffu, ss, o);
        float inv = 1.f / (sqrtf(ss) + EPSN);
        float* rowp = out2 + (size_t)row * (DIM + D_WEMB);
        ((float4*)rowp)[lane] = make_float4(aF.x*inv, aF.y*inv, aF.z*inv, aF.w*inv);
        float4* wr = (float4*)(rowp + DIM);
        wr[lane]      = make_float4(w0.x*inv, w0.y*inv, w0.z*inv, w0.w*inv);
        wr[lane + 32] = make_float4(w1.x*inv, w1.y*inv, w1.z*inv, w1.w*inv);
        if (lane < 11)
            wr[lane + 64] = make_float4(w2.x*inv, w2.y*inv, w2.z*inv, w2.w*inv);
    }
}

// ---------------------------------------------------------------------------
extern "C" void kernel_launch(void* const* d_in, const int* in_sizes, int n_in,
                              void* d_out, int out_size)
{
    const float* f1       = (const float*)d_in[0];
    const float* f2       = (const float*)d_in[1];
    const float* f3       = (const float*)d_in[2];
    const float* word_emb = (const float*)d_in[3];

    EdgePtrs ep;
    ep.r11 = (const int*)d_in[4];  ep.c11 = (const int*)d_in[5];  ep.v11 = (const float*)d_in[6];
    ep.r22 = (const int*)d_in[7];  ep.c22 = (const int*)d_in[8];  ep.v22 = (const float*)d_in[9];
    ep.r33 = (const int*)d_in[10]; ep.c33 = (const int*)d_in[11]; ep.v33 = (const float*)d_in[12];
    ep.r01 = (const int*)d_in[13]; ep.c01 = (const int*)d_in[14]; ep.v01 = (const float*)d_in[15];
    ep.r02 = (const int*)d_in[16]; ep.c02 = (const int*)d_in[17]; ep.v02 = (const float*)d_in[18];
    ep.r03 = (const int*)d_in[19]; ep.c03 = (const int*)d_in[20]; ep.v03 = (const float*)d_in[21];

    const float* W3   = (const float*)d_in[22];
    const float* b3   = (const float*)d_in[23];
    const float* W1_2 = (const float*)d_in[24];
    const float* b1_2 = (const float*)d_in[25];
    const float* W2_2 = (const float*)d_in[26];
    const float* b2_2 = (const float*)d_in[27];
    const float* W3_2 = (const float*)d_in[28];
    const float* b3_2 = (const float*)d_in[29];

    const int TB = 256;
    const int GRID_PREP = 2048 + 1;
    const int GRID_E    = (TOT_E + TB - 1) / TB;
    const int GRID_BKT  = (TOT_E / 2 + TB - 1) / TB;
    const int GRID_SPMM = ((N_WORD + N_ENT + N_POS) * 32 + TB - 1) / TB;
    const int GRID_GEMM = (((N_WORD + N_ENT + N_POS) / 4) * 32 + TB - 1) / TB;
    const int GRID_DOC  = (3 * N_DOC * 32 + TB - 1) / TB;

    prep_kernel<<<GRID_PREP, TB>>>(f1, f2, word_emb, f3, W3, b3);
    hist_kernel<<<GRID_E, TB>>>(ep);
    scan_kernel<<<1, 1024>>>();
    bucket_kernel<<<GRID_BKT, TB>>>(ep);

    spmm_l_kernel<1><<<GRID_SPMM, TB>>>();
    gemm_l2_kernel<<<GRID_GEMM, TB>>>(W1_2, b1_2, W2_2, b2_2, W3_2, b3_2);
    spmm_l_kernel<2><<<GRID_SPMM, TB>>>();

    docagg_kernel<<<GRID_DOC, TB>>>((float*)d_out);
}

// round 12
// speedup vs baseline: 1.4683x; 1.0424x over previous
#include <cuda_runtime.h>
#include <cuda_fp16.h>
#include <math.h>

// ---------------------------------------------------------------------------
// SHINE heterogeneous GCN — CSR counting sort (hist fused into prep),
// fp16-staged gather SpMM (2-acc, fp32 accumulate), f32x2 register-tiled GEMM,
// fused doc-agg + L2 norm.
// ---------------------------------------------------------------------------
#define N_DOC    10000
#define N_WORD   20000
#define N_ENT    10000
#define N_POS    60
#define DIM      128
#define D_POS_IN 60
#define D_WEMB   300
#define EPSN     1e-9f

#define E11 320000
#define E22 160000
#define E33 3600
#define E01 300000
#define E02 100000
#define E03 150000
#define TOT_E (E11 + E22 + E33 + E01 + E02 + E03)   // 1,033,600

// Counter-segment bases (order: a11, a22, a33, a01, a02, a03)
#define C11 0
#define C22 (C11 + N_WORD)   // 20000
#define C33 (C22 + N_ENT)    // 30000
#define C01 (C33 + N_POS)    // 30060
#define C02 (C01 + N_DOC)    // 40060
#define C03 (C02 + N_DOC)    // 50060
#define CTOT (C03 + N_DOC)   // 60060

// Edge-buffer segment bases (all even)
#define B11 0
#define B22 (B11 + E11)
#define B33 (B22 + E22)
#define B01 (B33 + E33)
#define B02 (B01 + E01)
#define B03 (B02 + E02)

// ---------------------------------------------------------------------------
// static scratch
__device__ __align__(16) float2 g_sorted[TOT_E];   // row-sorted (col_bits, val)
__device__ __align__(16) int    g_cnt[CTOT];
__device__ __align__(16) int    g_off[CTOT];       // after bucket: inclusive prefix

// fp16-staged gather sources
__device__ __align__(16) __half g_f1h  [N_WORD * DIM];
__device__ __align__(16) __half g_f2h  [N_ENT  * DIM];
__device__ __align__(16) __half g_wembh[N_ENT  * D_WEMB];
__device__ __align__(16) __half g_g1   [N_WORD * DIM];
__device__ __align__(16) __half g_g2   [N_ENT  * DIM];
__device__ __align__(16) __half g_g3   [N_POS  * DIM];
__device__ __align__(16) __half g_g3b  [N_POS  * DIM];
__device__ __align__(16) __half g_tmpB [N_WORD * DIM];
__device__ __align__(16) __half g_tmp2b[N_ENT  * DIM];
__device__ __align__(16) __half g_tmp3b[N_POS  * DIM];

// fp32 GEMM inputs (read linearly, not gathered)
__device__ __align__(16) float g_tmpA[N_WORD * DIM];
__device__ __align__(16) float g_tmp2[N_ENT  * DIM];
__device__ __align__(16) float g_tmp3[N_POS  * DIM];

struct EdgePtrs {
    const int *r11, *c11; const float *v11;
    const int *r22, *c22; const float *v22;
    const int *r33, *c33; const float *v33;
    const int *r01, *c01; const float *v01;
    const int *r02, *c02; const float *v02;
    const int *r03, *c03; const float *v03;
};

// ---------------------------------------------------------------------------
__device__ __forceinline__ float4 relu4(float4 t) {
    t.x = fmaxf(t.x, 0.f); t.y = fmaxf(t.y, 0.f);
    t.z = fmaxf(t.z, 0.f); t.w = fmaxf(t.w, 0.f);
    return t;
}
__device__ __forceinline__ void fma4(float4& a, float s, float4 t) {
    a.x = fmaf(s, t.x, a.x); a.y = fmaf(s, t.y, a.y);
    a.z = fmaf(s, t.z, a.z); a.w = fmaf(s, t.w, a.w);
}
__device__ __forceinline__ float dot4(float4 a) {
    return a.x * a.x + a.y * a.y + a.z * a.z + a.w * a.w;
}
// 8B load of 4 halves -> float4
__device__ __forceinline__ float4 ldg_h4(const __half* base, int unit) {
    uint2 u = __ldg((const uint2*)base + unit);
    __half2 a = *reinterpret_cast<__half2*>(&u.x);
    __half2 b = *reinterpret_cast<__half2*>(&u.y);
    float2 fa = __half22float2(a), fb = __half22float2(b);
    return make_float4(fa.x, fa.y, fb.x, fb.y);
}
__device__ __forceinline__ void st_h4(__half* base, int unit, float4 v) {
    __half2 a = __floats2half2_rn(v.x, v.y);
    __half2 b = __floats2half2_rn(v.z, v.w);
    uint2 u;
    u.x = *reinterpret_cast<unsigned*>(&a);
    u.y = *reinterpret_cast<unsigned*>(&b);
    ((uint2*)base)[unit] = u;
}

// ---- packed f32x2 helpers (sm_103a FFMA2 path; ptxas never emits from C++) --
__device__ __forceinline__ unsigned long long pack2(float x, float y) {
    unsigned long long r;
    asm("mov.b64 %0, {%1, %2};" : "=l"(r) : "f"(x), "f"(y));
    return r;
}
__device__ __forceinline__ void unpack2(unsigned long long p, float& x, float& y) {
    asm("mov.b64 {%0, %1}, %2;" : "=f"(x), "=f"(y) : "l"(p));
}
__device__ __forceinline__ void fma2(unsigned long long& d,
                                     unsigned long long a, unsigned long long b) {
    asm("fma.rn.f32x2 %0, %1, %2, %3;" : "=l"(d) : "l"(a), "l"(b), "l"(d));
}

// ---------------------------------------------------------------------------
// register-tiled GEMM: one warp computes 4 rows x 128 cols using f32x2 FMA.
__device__ __forceinline__ void gemm_store(float* p, int lane, float4 v) {
    ((float4*)p)[lane] = v;
}
__device__ __forceinline__ void gemm_store(__half* p, int lane, float4 v) {
    st_h4(p, lane, v);
}

template <bool RELU_A, typename OutT>
__device__ __forceinline__ void gemm4_rows(const float* __restrict__ A,
                                           const float* __restrict__ W,
                                           const float* __restrict__ bias,
                                           OutT* __restrict__ C,
                                           int r0, int K, int lane)
{
    float4 a0 = make_float4(0,0,0,0), a1 = a0, a2 = a0, a3 = a0;
    if (4 * lane < K) {
        a0 = *(const float4*)(A + (size_t)(r0 + 0) * K + 4 * lane);
        a1 = *(const float4*)(A + (size_t)(r0 + 1) * K + 4 * lane);
        a2 = *(const float4*)(A + (size_t)(r0 + 2) * K + 4 * lane);
        a3 = *(const float4*)(A + (size_t)(r0 + 3) * K + 4 * lane);
        if (RELU_A) { a0 = relu4(a0); a1 = relu4(a1); a2 = relu4(a2); a3 = relu4(a3); }
    }
    float4 bf = __ldg((const float4*)bias + lane);
    unsigned long long c0x = pack2(bf.x, bf.y), c0y = pack2(bf.z, bf.w);
    unsigned long long c1x = c0x, c1y = c0y, c2x = c0x, c2y = c0y, c3x = c0x, c3y = c0y;

    for (int k = 0; k < K; k += 4) {
        int src = k >> 2;
        #pragma unroll
        for (int kk = 0; kk < 4; kk++) {
            ulonglong2 wv = __ldg((const ulonglong2*)(W + (size_t)(k + kk) * DIM) + lane);
            float s0 = __shfl_sync(0xffffffffu, ((const float*)&a0)[kk], src);
            float s1 = __shfl_sync(0xffffffffu, ((const float*)&a1)[kk], src);
            float s2 = __shfl_sync(0xffffffffu, ((const float*)&a2)[kk], src);
            float s3 = __shfl_sync(0xffffffffu, ((const float*)&a3)[kk], src);
            unsigned long long p0 = pack2(s0, s0), p1 = pack2(s1, s1);
            unsigned long long p2 = pack2(s2, s2), p3 = pack2(s3, s3);
            fma2(c0x, p0, wv.x); fma2(c0y, p0, wv.y);
            fma2(c1x, p1, wv.x); fma2(c1y, p1, wv.y);
            fma2(c2x, p2, wv.x); fma2(c2y, p2, wv.y);
            fma2(c3x, p3, wv.x); fma2(c3y, p3, wv.y);
        }
    }
    float4 r;
    unpack2(c0x, r.x, r.y); unpack2(c0y, r.z, r.w);
    gemm_store(C + (size_t)(r0 + 0) * DIM, lane, r);
    unpack2(c1x, r.x, r.y); unpack2(c1y, r.z, r.w);
    gemm_store(C + (size_t)(r0 + 1) * DIM, lane, r);
    unpack2(c2x, r.x, r.y); unpack2(c2y, r.z, r.w);
    gemm_store(C + (size_t)(r0 + 2) * DIM, lane, r);
    unpack2(c3x, r.x, r.y); unpack2(c3y, r.z, r.w);
    gemm_store(C + (size_t)(r0 + 3) * DIM, lane, r);
}

// ---------------------------------------------------------------------------
// 0) prep: histogram (2 edges/thread) + fp16 conversion + POS layer-1 GEMM,
//    partitioned by block range. g_cnt zeroed by cudaMemsetAsync beforehand.
#define F1U  (N_WORD * DIM / 4)      // 640000
#define F2U  (N_ENT  * DIM / 4)      // 320000
#define WEU  (N_ENT  * D_WEMB / 4)   // 750000
#define CONV_UNITS (F1U + F2U + WEU) // 1,710,000
#define GB_HISTP ((TOT_E / 2 + 255) / 256)   // 2019
#define GB_CONV 2048

__global__ void prep_kernel(EdgePtrs ep,
                            const float* __restrict__ f1, const float* __restrict__ f2,
                            const float* __restrict__ wemb, const float* __restrict__ f3,
                            const float* __restrict__ W3, const float* __restrict__ b3)
{
    int b = blockIdx.x;
    if (b < GB_HISTP) {
        // histogram, 2 edges per thread (all segment bases even)
        int p = b * blockDim.x + threadIdx.x;
        if (p >= TOT_E / 2) return;
        int e = 2 * p;
        const int* rp; int cb;
        if (e < B22)      { rp = ep.r11; cb = C11; e -= B11; }
        else if (e < B33) { rp = ep.r22; cb = C22; e -= B22; }
        else if (e < B01) { rp = ep.r33; cb = C33; e -= B33; }
        else if (e < B02) { rp = ep.r01; cb = C01; e -= B01; }
        else if (e < B03) { rp = ep.r02; cb = C02; e -= B02; }
        else              { rp = ep.r03; cb = C03; e -= B03; }
        int2 r = __ldg((const int2*)rp + (e >> 1));
        atomicAdd(g_cnt + cb + r.x, 1);
        atomicAdd(g_cnt + cb + r.y, 1);
    } else if (b < GB_HISTP + GB_CONV) {
        int stride = GB_CONV * blockDim.x;
        for (int u = (b - GB_HISTP) * blockDim.x + threadIdx.x; u < CONV_UNITS; u += stride) {
            if (u < F1U) {
                st_h4(g_f1h, u, __ldg((const float4*)f1 + u));
            } else if (u < F1U + F2U) {
                int i = u - F1U;
                st_h4(g_f2h, i, __ldg((const float4*)f2 + i));
            } else {
                int i = u - (F1U + F2U);
                st_h4(g_wembh, i, __ldg((const float4*)wemb + i));
            }
        }
    } else {
        // POS layer-1 GEMM: 60 rows -> 15 warp-tasks
        int lane = threadIdx.x & 31;
        for (int w = threadIdx.x >> 5; w < N_POS / 4; w += blockDim.x >> 5)
            gemm4_rows<false>(f3, W3, b3, g_g3, 4 * w, D_POS_IN, lane);
    }
}

// ---------------------------------------------------------------------------
// 1) single-block exclusive scan of the counters -> g_off
__global__ void scan_kernel() {
    __shared__ int sp[1024];
    const int tid = threadIdx.x;
    const int per = (CTOT + 1023) / 1024;   // 59
    int lo = tid * per;
    int hi = lo + per; if (hi > CTOT) hi = CTOT;
    if (lo > CTOT) lo = CTOT;
    int s = 0;
    for (int i = lo; i < hi; i++) s += g_cnt[i];
    sp[tid] = s;
    __syncthreads();
    for (int d = 1; d < 1024; d <<= 1) {
        int v = (tid >= d) ? sp[tid - d] : 0;
        __syncthreads();
        sp[tid] += v;
        __syncthreads();
    }
    int run = (tid > 0) ? sp[tid - 1] : 0;
    for (int i = lo; i < hi; i++) {
        g_off[i] = run;
        run += g_cnt[i];
    }
}

// 2) bucket scatter, 2 edges per thread; bumps g_off in place
//    (afterwards g_off[i] = inclusive prefix).
__global__ void bucket_kernel(EdgePtrs ep) {
    int p = blockIdx.x * blockDim.x + threadIdx.x;   // pair index
    if (p >= TOT_E / 2) return;
    int e = 2 * p;
    const int *rp, *cp; const float *vp; int cb;
    if (e < B22)      { rp = ep.r11; cp = ep.c11; vp = ep.v11; cb = C11; e -= B11; }
    else if (e < B33) { rp = ep.r22; cp = ep.c22; vp = ep.v22; cb = C22; e -= B22; }
    else if (e < B01) { rp = ep.r33; cp = ep.c33; vp = ep.v33; cb = C33; e -= B33; }
    else if (e < B02) { rp = ep.r01; cp = ep.c01; vp = ep.v01; cb = C01; e -= B01; }
    else if (e < B03) { rp = ep.r02; cp = ep.c02; vp = ep.v02; cb = C02; e -= B02; }
    else              { rp = ep.r03; cp = ep.c03; vp = ep.v03; cb = C03; e -= B03; }
    int h = e >> 1;
    int2   r = __ldg((const int2*)rp + h);
    int2   c = __ldg((const int2*)cp + h);
    float2 v = __ldg((const float2*)vp + h);
    int pos0 = atomicAdd(g_off + cb + r.x, 1);
    int pos1 = atomicAdd(g_off + cb + r.y, 1);
    g_sorted[pos0] = make_float2(__int_as_float(c.x), v.x);
    g_sorted[pos1] = make_float2(__int_as_float(c.y), v.y);
}

// ---------------------------------------------------------------------------
// gather SpMM row accumulator over fp16 source; warp-per-row, float4/lane.
// 2 accumulators, 2 edges in flight (the proven low-register configuration).
template <bool RELU>
__device__ __forceinline__ float4 spmm_row_acc_h(int gi, const __half* __restrict__ x, int lane) {
    int s = (gi == 0) ? 0 : __ldg(g_off + gi - 1);
    int e = __ldg(g_off + gi);
    float4 acc0 = make_float4(0.f, 0.f, 0.f, 0.f);
    float4 acc1 = acc0;
    int k = s;
    for (; k + 1 < e; k += 2) {
        float2 cv0 = __ldg(&g_sorted[k]);
        float2 cv1 = __ldg(&g_sorted[k + 1]);
        float4 t0 = ldg_h4(x + (size_t)__float_as_int(cv0.x) * DIM, lane);
        float4 t1 = ldg_h4(x + (size_t)__float_as_int(cv1.x) * DIM, lane);
        if (RELU) { t0 = relu4(t0); t1 = relu4(t1); }
        fma4(acc0, cv0.y, t0);
        fma4(acc1, cv1.y, t1);
    }
    if (k < e) {
        float2 cv = __ldg(&g_sorted[k]);
        float4 t = ldg_h4(x + (size_t)__float_as_int(cv.x) * DIM, lane);
        if (RELU) t = relu4(t);
        fma4(acc0, cv.y, t);
    }
    acc0.x += acc1.x; acc0.y += acc1.y; acc0.z += acc1.z; acc0.w += acc1.w;
    return acc0;
}

// 3/5) fused layer-1 / layer-2 SpMM over all three node types
template <int LAYER>
__global__ void spmm_l_kernel() {
    int w    = (blockIdx.x * blockDim.x + threadIdx.x) >> 5;
    int lane = threadIdx.x & 31;
    if (w >= N_WORD + N_ENT + N_POS) return;
    const __half* x; void* outp; int gi;
    if (w < N_WORD) {
        gi = C11 + w;
        x = (LAYER == 1) ? g_f1h : g_g1;
        outp = (LAYER == 1) ? (void*)(g_tmpA + (size_t)w * DIM)
                            : (void*)(g_tmpB + (size_t)w * DIM);
    } else if (w < N_WORD + N_ENT) {
        int r = w - N_WORD;
        gi = C22 + r;
        x = (LAYER == 1) ? g_f2h : g_g2;
        outp = (LAYER == 1) ? (void*)(g_tmp2 + (size_t)r * DIM)
                            : (void*)(g_tmp2b + (size_t)r * DIM);
    } else {
        int r = w - (N_WORD + N_ENT);
        gi = C33 + r;
        x = (LAYER == 1) ? g_g3 : g_g3b;
        outp = (LAYER == 1) ? (void*)(g_tmp3 + (size_t)r * DIM)
                            : (void*)(g_tmp3b + (size_t)r * DIM);
    }
    float4 acc = spmm_row_acc_h<false>(gi, x, lane);
    if (LAYER == 1) ((float4*)outp)[lane] = acc;
    else            st_h4((__half*)outp, lane, acc);
}

// 4) fused layer-2 projections for all three types (relu on input): K=128
__global__ void gemm_l2_kernel(const float* __restrict__ W1, const float* __restrict__ b1,
                               const float* __restrict__ W2, const float* __restrict__ b2,
                               const float* __restrict__ Wp, const float* __restrict__ bp) {
    int w    = (blockIdx.x * blockDim.x + threadIdx.x) >> 5;
    int lane = threadIdx.x & 31;
    const int WW = N_WORD / 4, WE = WW + N_ENT / 4, WP = WE + N_POS / 4;
    if (w >= WP) return;
    if (w < WW)       gemm4_rows<true>(g_tmpA, W1, b1, g_g1,  4 * w,        DIM, lane);
    else if (w < WE)  gemm4_rows<true>(g_tmp2, W2, b2, g_g2,  4 * (w - WW), DIM, lane);
    else              gemm4_rows<true>(g_tmp3, Wp, bp, g_g3b, 4 * (w - WE), DIM, lane);
}

// ---------------------------------------------------------------------------
// 6) fused doc aggregation + relu(source) + wemb concat + L2 norm
__global__ void docagg_kernel(float* __restrict__ out) {
    int w    = (blockIdx.x * blockDim.x + threadIdx.x) >> 5;
    int lane = threadIdx.x & 31;
    if (w >= 3 * N_DOC) return;
    float* out1 = out;
    float* out2 = out + (size_t)N_DOC * DIM;
    float* out3 = out2 + (size_t)N_DOC * (DIM + D_WEMB);

    if (w < N_DOC || w >= 2 * N_DOC) {
        bool first = (w < N_DOC);
        int row = first ? w : (w - 2 * N_DOC);
        int gi  = first ? (C01 + row) : (C03 + row);
        const __half* x = first ? g_tmpB : g_tmp3b;
        float4 acc = spmm_row_acc_h<true>(gi, x, lane);
        float ss = dot4(acc);
        #pragma unroll
        for (int o = 16; o; o >>= 1) ss += __shfl_xor_sync(0xffffffffu, ss, o);
        float inv = 1.f / (sqrtf(ss) + EPSN);
        float* dst = (first ? out1 : out3) + (size_t)row * DIM;
        ((float4*)dst)[lane] = make_float4(acc.x*inv, acc.y*inv, acc.z*inv, acc.w*inv);
    } else {
        // entities -> out2: 128 feature cols + 300 word_emb cols, norm over 428
        int row = w - N_DOC;
        int gi = C02 + row;
        int s = __ldg(g_off + gi - 1);
        int e = __ldg(g_off + gi);
        float4 aF = make_float4(0,0,0,0), w0 = aF, w1 = aF, w2 = aF;
        #pragma unroll 2
        for (int k = s; k < e; ++k) {
            float2 cv = __ldg(&g_sorted[k]);
            int c = __float_as_int(cv.x);
            float v = cv.y;
            float4 t = relu4(ldg_h4(g_tmp2b + (size_t)c * DIM, lane));
            fma4(aF, v, t);
            const __half* ws = g_wembh + (size_t)c * D_WEMB;  // 75 h4-units
            fma4(w0, v, ldg_h4(ws, lane));
            fma4(w1, v, ldg_h4(ws, lane + 32));
            if (lane < 11) fma4(w2, v, ldg_h4(ws, lane + 64));
        }
        float ss = dot4(aF) + dot4(w0) + dot4(w1);
        if (lane < 11) ss += dot4(w2);
        #pragma unroll
        for (int o = 16; o; o >>= 1) ss += __shfl_xor_sync(0xffffffffu, ss, o);
        float inv = 1.f / (sqrtf(ss) + EPSN);
        float* rowp = out2 + (size_t)row * (DIM + D_WEMB);
        ((float4*)rowp)[lane] = make_float4(aF.x*inv, aF.y*inv, aF.z*inv, aF.w*inv);
        float4* wr = (float4*)(rowp + DIM);
        wr[lane]      = make_float4(w0.x*inv, w0.y*inv, w0.z*inv, w0.w*inv);
        wr[lane + 32] = make_float4(w1.x*inv, w1.y*inv, w1.z*inv, w1.w*inv);
        if (lane < 11)
            wr[lane + 64] = make_float4(w2.x*inv, w2.y*inv, w2.z*inv, w2.w*inv);
    }
}

// ---------------------------------------------------------------------------
extern "C" void kernel_launch(void* const* d_in, const int* in_sizes, int n_in,
                              void* d_out, int out_size)
{
    const float* f1       = (const float*)d_in[0];
    const float* f2       = (const float*)d_in[1];
    const float* f3       = (const float*)d_in[2];
    const float* word_emb = (const float*)d_in[3];

    EdgePtrs ep;
    ep.r11 = (const int*)d_in[4];  ep.c11 = (const int*)d_in[5];  ep.v11 = (const float*)d_in[6];
    ep.r22 = (const int*)d_in[7];  ep.c22 = (const int*)d_in[8];  ep.v22 = (const float*)d_in[9];
    ep.r33 = (const int*)d_in[10]; ep.c33 = (const int*)d_in[11]; ep.v33 = (const float*)d_in[12];
    ep.r01 = (const int*)d_in[13]; ep.c01 = (const int*)d_in[14]; ep.v01 = (const float*)d_in[15];
    ep.r02 = (const int*)d_in[16]; ep.c02 = (const int*)d_in[17]; ep.v02 = (const float*)d_in[18];
    ep.r03 = (const int*)d_in[19]; ep.c03 = (const int*)d_in[20]; ep.v03 = (const float*)d_in[21];

    const float* W3   = (const float*)d_in[22];
    const float* b3   = (const float*)d_in[23];
    const float* W1_2 = (const float*)d_in[24];
    const float* b1_2 = (const float*)d_in[25];
    const float* W2_2 = (const float*)d_in[26];
    const float* b2_2 = (const float*)d_in[27];
    const float* W3_2 = (const float*)d_in[28];
    const float* b3_2 = (const float*)d_in[29];

    void* cnt_addr = nullptr;
    cudaGetSymbolAddress(&cnt_addr, g_cnt);

    const int TB = 256;
    const int GRID_PREP = GB_HISTP + GB_CONV + 1;
    const int GRID_BKT  = (TOT_E / 2 + TB - 1) / TB;
    const int GRID_SPMM = ((N_WORD + N_ENT + N_POS) * 32 + TB - 1) / TB;
    const int GRID_GEMM = (((N_WORD + N_ENT + N_POS) / 4) * 32 + TB - 1) / TB;
    const int GRID_DOC  = (3 * N_DOC * 32 + TB - 1) / TB;

    cudaMemsetAsync(cnt_addr, 0, CTOT * sizeof(int), 0);
    prep_kernel<<<GRID_PREP, TB>>>(ep, f1, f2, word_emb, f3, W3, b3);
    scan_kernel<<<1, 1024>>>();
    bucket_kernel<<<GRID_BKT, TB>>>(ep);

    spmm_l_kernel<1><<<GRID_SPMM, TB>>>();
    gemm_l2_kernel<<<GRID_GEMM, TB>>>(W1_2, b1_2, W2_2, b2_2, W3_2, b3_2);
    spmm_l_kernel<2><<<GRID_SPMM, TB>>>();

    docagg_kernel<<<GRID_DOC, TB>>>((float*)d_out);
}